// round 1
// baseline (speedup 1.0000x reference)
#include <cuda_runtime.h>
#include <math.h>

#define Hh 12
#define Ee 768
#define Dd 64
#define LLen 2048
#define Bb 2
#define Mrows (Bb*LLen)      // 4096
#define N3E (3*Ee)           // 2304
#define LORA 8.0f

// ---------------- scratch (static device globals; no allocation) ----------------
__device__ float g_w1[Ee * N3E];     // fused LoRA input weights  [768, 2304]
__device__ float g_w2[Ee * Ee];      // fused LoRA output weights [768, 768]
__device__ float g_c [Mrows * N3E];  // qkv activations           [4096, 2304]
__device__ float g_a [Mrows * Ee];   // attention output          [4096, 768]

// ---------------- weight prep: w + 8 * B @ A ----------------
__global__ void prep_w(const float* __restrict__ w_in, const float* __restrict__ A_in,
                       const float* __restrict__ B_in, const float* __restrict__ w_out,
                       const float* __restrict__ A_out, const float* __restrict__ B_out)
{
    int i = blockIdx.x * blockDim.x + threadIdx.x;
    if (i < Ee * N3E) {
        int e = i / N3E, o = i - e * N3E;
        float s = 0.f;
        #pragma unroll
        for (int r = 0; r < 4; r++) s += B_in[e*4 + r] * A_in[r*N3E + o];
        g_w1[i] = w_in[i] + LORA * s;
    }
    if (i < Ee * Ee) {
        int e = i / Ee, o = i - e * Ee;
        float s = 0.f;
        #pragma unroll
        for (int r = 0; r < 4; r++) s += B_out[e*4 + r] * A_out[r*Ee + o];
        g_w2[i] = w_out[i] + LORA * s;
    }
}

// ---------------- SGEMM: C[M,N] = A[M,768] * B[768,N] + bias[N] ----------------
// 128x128 tile, Kstep=8, 256 threads, 8x8 per thread. M,N multiples of 128.
__global__ void __launch_bounds__(256)
sgemm_bias(const float* __restrict__ A, const float* __restrict__ Bw,
           const float* __restrict__ bias, float* __restrict__ C, int N)
{
    __shared__ float As[8][128];
    __shared__ float Bs[8][128];

    const int tid = threadIdx.x;
    const int m0 = blockIdx.y * 128;
    const int n0 = blockIdx.x * 128;
    const int rm = (tid >> 4) * 8;
    const int rn = (tid & 15) * 8;

    const int arow  = tid >> 1;            // 0..127
    const int akseg = (tid & 1) * 4;       // 0 or 4
    const int bkk   = tid >> 5;            // 0..7
    const int bns   = (tid & 31) * 4;      // 0..124

    float acc[8][8];
    #pragma unroll
    for (int i = 0; i < 8; i++)
        #pragma unroll
        for (int j = 0; j < 8; j++) acc[i][j] = 0.f;

    for (int k0 = 0; k0 < 768; k0 += 8) {
        float4 av = *(const float4*)&A[(size_t)(m0 + arow) * 768 + k0 + akseg];
        As[akseg+0][arow] = av.x; As[akseg+1][arow] = av.y;
        As[akseg+2][arow] = av.z; As[akseg+3][arow] = av.w;
        float4 bv = *(const float4*)&Bw[(size_t)(k0 + bkk) * N + n0 + bns];
        *(float4*)&Bs[bkk][bns] = bv;
        __syncthreads();

        #pragma unroll
        for (int kk = 0; kk < 8; kk++) {
            float a[8], b[8];
            *(float4*)&a[0] = *(float4*)&As[kk][rm];
            *(float4*)&a[4] = *(float4*)&As[kk][rm + 4];
            *(float4*)&b[0] = *(float4*)&Bs[kk][rn];
            *(float4*)&b[4] = *(float4*)&Bs[kk][rn + 4];
            #pragma unroll
            for (int i = 0; i < 8; i++)
                #pragma unroll
                for (int j = 0; j < 8; j++)
                    acc[i][j] += a[i] * b[j];
        }
        __syncthreads();
    }

    float bz[8];
    #pragma unroll
    for (int j = 0; j < 8; j++) bz[j] = bias[n0 + rn + j];

    #pragma unroll
    for (int i = 0; i < 8; i++) {
        float4 v0, v1;
        v0.x = acc[i][0] + bz[0]; v0.y = acc[i][1] + bz[1];
        v0.z = acc[i][2] + bz[2]; v0.w = acc[i][3] + bz[3];
        v1.x = acc[i][4] + bz[4]; v1.y = acc[i][5] + bz[5];
        v1.z = acc[i][6] + bz[6]; v1.w = acc[i][7] + bz[7];
        float* crow = &C[(size_t)(m0 + rm + i) * N + n0 + rn];
        *(float4*)&crow[0] = v0;
        *(float4*)&crow[4] = v1;
    }
}

// ---------------- flash attention (fp32, causal, no scale) ----------------
// grid: (L/64, B*H). 256 threads, 64x64 Q-tile x 64-wide K/V tiles.
// Thread (ty,tx): rows r0=4ty..+3 of tile; S cols c_j = tx+16j; O cols d0=4tx..+3.
__global__ void __launch_bounds__(256)
flash_attn()
{
    __shared__ float Qs[64][64];    // [r][d], row-major
    __shared__ float KsF[64 * 64];  // [c][d] XOR-swizzled at float4 granularity; reused as Ps[r][c]
    __shared__ float Vs[64][64];    // [k][d]

    const int tid = threadIdx.x;
    const int tx = tid & 15;
    const int ty = tid >> 4;
    const int qb = blockIdx.x * 64;
    const int bh = blockIdx.y;
    const int b  = bh / Hh;
    const int h  = bh - b * Hh;

    const float* qg = g_c + (size_t)(b * LLen) * N3E + h * Dd;
    const float* kg = qg + Ee;
    const float* vg = qg + 2 * Ee;

    // load Q tile (row-major, conflict-free)
    #pragma unroll
    for (int i = 0; i < 4; i++) {
        int f4 = tid + i * 256;
        int r  = f4 >> 4;
        int dd = f4 & 15;
        float4 v = *(const float4*)&qg[(size_t)(qb + r) * N3E + dd * 4];
        *(float4*)&Qs[r][dd * 4] = v;
    }

    const int r0 = ty * 4;
    const int cj0 = tx; // c_j = tx + 16*j

    float m[4]  = {-INFINITY, -INFINITY, -INFINITY, -INFINITY};
    float l[4]  = {0.f, 0.f, 0.f, 0.f};
    float o[4][4];
    #pragma unroll
    for (int i = 0; i < 4; i++)
        #pragma unroll
        for (int j = 0; j < 4; j++) o[i][j] = 0.f;

    for (int kb = 0; kb <= qb; kb += 64) {
        // load K (swizzled) and V (plain)
        #pragma unroll
        for (int i = 0; i < 4; i++) {
            int f4 = tid + i * 256;
            int c  = f4 >> 4;
            int dd = f4 & 15;
            float4 kv = *(const float4*)&kg[(size_t)(kb + c) * N3E + dd * 4];
            *(float4*)&KsF[c * 64 + ((dd ^ (c & 15)) << 2)] = kv;
            float4 vv = *(const float4*)&vg[(size_t)(kb + c) * N3E + dd * 4];
            *(float4*)&Vs[c][dd * 4] = vv;
        }
        __syncthreads();

        // S = Q K^T  (4x4 per thread, cols strided by 16)
        float s[4][4];
        #pragma unroll
        for (int i = 0; i < 4; i++)
            #pragma unroll
            for (int j = 0; j < 4; j++) s[i][j] = 0.f;

        #pragma unroll 4
        for (int dc = 0; dc < 16; dc++) {
            float q[4][4], kreg[4][4];
            #pragma unroll
            for (int i = 0; i < 4; i++)
                *(float4*)q[i] = *(float4*)&Qs[r0 + i][dc * 4];
            #pragma unroll
            for (int j = 0; j < 4; j++)
                *(float4*)kreg[j] = *(float4*)&KsF[(cj0 + 16 * j) * 64 + ((dc ^ tx) << 2)];
            #pragma unroll
            for (int i = 0; i < 4; i++)
                #pragma unroll
                for (int j = 0; j < 4; j++) {
                    s[i][j] += q[i][0] * kreg[j][0];
                    s[i][j] += q[i][1] * kreg[j][1];
                    s[i][j] += q[i][2] * kreg[j][2];
                    s[i][j] += q[i][3] * kreg[j][3];
                }
        }

        // causal mask on diagonal tile
        if (kb == qb) {
            #pragma unroll
            for (int i = 0; i < 4; i++)
                #pragma unroll
                for (int j = 0; j < 4; j++)
                    if (cj0 + 16 * j > r0 + i) s[i][j] = -1e9f;
        }

        // online softmax
        #pragma unroll
        for (int i = 0; i < 4; i++) {
            float mt = fmaxf(fmaxf(s[i][0], s[i][1]), fmaxf(s[i][2], s[i][3]));
            #pragma unroll
            for (int off = 8; off > 0; off >>= 1)
                mt = fmaxf(mt, __shfl_xor_sync(0xffffffffu, mt, off));
            float mn = fmaxf(m[i], mt);
            float sc = __expf(m[i] - mn);
            m[i] = mn;
            float ls = 0.f;
            #pragma unroll
            for (int j = 0; j < 4; j++) {
                s[i][j] = __expf(s[i][j] - mn);
                ls += s[i][j];
            }
            #pragma unroll
            for (int off = 8; off > 0; off >>= 1)
                ls += __shfl_xor_sync(0xffffffffu, ls, off);
            l[i] = l[i] * sc + ls;
            #pragma unroll
            for (int j = 0; j < 4; j++) o[i][j] *= sc;
        }

        __syncthreads();   // everyone done reading KsF

        // store P into KsF region as plain Ps[r][c]
        float* Ps = KsF;
        #pragma unroll
        for (int i = 0; i < 4; i++)
            #pragma unroll
            for (int j = 0; j < 4; j++)
                Ps[(r0 + i) * 64 + cj0 + 16 * j] = s[i][j];
        __syncthreads();

        // O += P V
        #pragma unroll 4
        for (int k4 = 0; k4 < 64; k4 += 4) {
            float p[4][4], v[4][4];
            #pragma unroll
            for (int i = 0; i < 4; i++)
                *(float4*)p[i] = *(float4*)&Ps[(r0 + i) * 64 + k4];
            #pragma unroll
            for (int kk = 0; kk < 4; kk++)
                *(float4*)v[kk] = *(float4*)&Vs[k4 + kk][tx * 4];
            #pragma unroll
            for (int i = 0; i < 4; i++)
                #pragma unroll
                for (int j = 0; j < 4; j++) {
                    o[i][j] += p[i][0] * v[0][j];
                    o[i][j] += p[i][1] * v[1][j];
                    o[i][j] += p[i][2] * v[2][j];
                    o[i][j] += p[i][3] * v[3][j];
                }
        }
        __syncthreads();   // before next tile's K/V overwrite
    }

    // normalize & store to g_a[b*L+qb+r][h*64 + 4tx .. +3]
    float* ag = g_a + (size_t)(b * LLen + qb) * Ee + h * Dd;
    #pragma unroll
    for (int i = 0; i < 4; i++) {
        float inv = 1.f / l[i];
        float4 v;
        v.x = o[i][0] * inv; v.y = o[i][1] * inv;
        v.z = o[i][2] * inv; v.w = o[i][3] * inv;
        *(float4*)&ag[(size_t)(r0 + i) * Ee + tx * 4] = v;
    }
}

// ---------------- launch ----------------
extern "C" void kernel_launch(void* const* d_in, const int* in_sizes, int n_in,
                              void* d_out, int out_size)
{
    const float* x     = (const float*)d_in[0];
    const float* w_in  = (const float*)d_in[1];
    const float* b_in  = (const float*)d_in[2];
    const float* A_in  = (const float*)d_in[3];
    const float* B_in  = (const float*)d_in[4];
    const float* w_out = (const float*)d_in[5];
    const float* b_out = (const float*)d_in[6];
    const float* A_out = (const float*)d_in[7];
    const float* B_out = (const float*)d_in[8];
    float* out = (float*)d_out;

    float *p_w1, *p_w2, *p_c, *p_a;
    cudaGetSymbolAddress((void**)&p_w1, g_w1);
    cudaGetSymbolAddress((void**)&p_w2, g_w2);
    cudaGetSymbolAddress((void**)&p_c,  g_c);
    cudaGetSymbolAddress((void**)&p_a,  g_a);

    // 1) fuse LoRA into weights
    {
        int total = Ee * N3E;
        prep_w<<<(total + 255) / 256, 256>>>(w_in, A_in, B_in, w_out, A_out, B_out);
    }
    // 2) QKV projection: c = x @ w1 + b_in   [4096, 2304]
    {
        dim3 grid(N3E / 128, Mrows / 128);
        sgemm_bias<<<grid, 256>>>(x, p_w1, b_in, p_c, N3E);
    }
    // 3) causal attention -> g_a [4096, 768]
    {
        dim3 grid(LLen / 64, Bb * Hh);
        flash_attn<<<grid, 256>>>();
    }
    // 4) output projection: out = a @ w2 + b_out
    {
        dim3 grid(Ee / 128, Mrows / 128);
        sgemm_bias<<<grid, 256>>>(p_a, p_w2, b_out, out, Ee);
    }
}

// round 2
// speedup vs baseline: 1.0803x; 1.0803x over previous
#include <cuda_runtime.h>
#include <math.h>

#define Hh 12
#define Ee 768
#define Dd 64
#define LLen 2048
#define Bb 2
#define Mrows (Bb*LLen)      // 4096
#define N3E (3*Ee)           // 2304
#define LORA 8.0f

// ---------------- scratch ----------------
__device__ float g_w1[Ee * N3E];
__device__ float g_w2[Ee * Ee];
__device__ float g_c [Mrows * N3E];
__device__ float g_a [Mrows * Ee];

// ---------------- weight prep: w + 8 * B @ A ----------------
__global__ void prep_w(const float* __restrict__ w_in, const float* __restrict__ A_in,
                       const float* __restrict__ B_in, const float* __restrict__ w_out,
                       const float* __restrict__ A_out, const float* __restrict__ B_out)
{
    int i = blockIdx.x * blockDim.x + threadIdx.x;
    if (i < Ee * N3E) {
        int e = i / N3E, o = i - e * N3E;
        float s = 0.f;
        #pragma unroll
        for (int r = 0; r < 4; r++) s += B_in[e*4 + r] * A_in[r*N3E + o];
        g_w1[i] = w_in[i] + LORA * s;
    }
    if (i < Ee * Ee) {
        int e = i / Ee, o = i - e * Ee;
        float s = 0.f;
        #pragma unroll
        for (int r = 0; r < 4; r++) s += B_out[e*4 + r] * A_out[r*Ee + o];
        g_w2[i] = w_out[i] + LORA * s;
    }
}

// ---------------- double-buffered SGEMM: C[M,N] = A[M,768]*B[768,N] + bias ----------------
// 128 x TN tile, Kstep=8, 256 threads. TN=128 -> 8x8/thread, TN=64 -> 8x4/thread.
template<int TN>
__global__ void __launch_bounds__(256)
sgemm_bias(const float* __restrict__ A, const float* __restrict__ Bw,
           const float* __restrict__ bias, float* __restrict__ C, int N)
{
    constexpr int JN = TN / 16;   // 8 or 4
    __shared__ float As[2][8][128];
    __shared__ float Bs[2][8][TN];

    const int tid = threadIdx.x;
    const int m0 = blockIdx.y * 128;
    const int n0 = blockIdx.x * TN;
    const int rm = (tid >> 4) * 8;       // 8 rows
    const int tx = tid & 15;             // col group

    // A-load mapping: 128 rows x 8 k, each thread one float4
    const int arow  = tid >> 1;
    const int akseg = (tid & 1) * 4;
    // B-load mapping
    int bkk, bns;
    if (TN == 128) { bkk = tid >> 5; bns = (tid & 31) * 4; }
    else           { bkk = tid >> 4; bns = (tid & 15) * 4; }   // only tid<128 active

    float acc[8][JN];
    #pragma unroll
    for (int i = 0; i < 8; i++)
        #pragma unroll
        for (int j = 0; j < JN; j++) acc[i][j] = 0.f;

    // preload tile 0
    {
        float4 av = *(const float4*)&A[(size_t)(m0 + arow) * 768 + akseg];
        As[0][akseg+0][arow] = av.x; As[0][akseg+1][arow] = av.y;
        As[0][akseg+2][arow] = av.z; As[0][akseg+3][arow] = av.w;
        if (TN == 128 || tid < 128) {
            float4 bv = *(const float4*)&Bw[(size_t)bkk * N + n0 + bns];
            *(float4*)&Bs[0][bkk][bns] = bv;
        }
    }
    __syncthreads();

    const int NIT = 768 / 8;
    for (int it = 0; it < NIT; ++it) {
        const int cur = it & 1;
        float4 av, bv;
        const bool has = (it + 1 < NIT);
        if (has) {
            int k0 = (it + 1) * 8;
            av = *(const float4*)&A[(size_t)(m0 + arow) * 768 + k0 + akseg];
            if (TN == 128 || tid < 128)
                bv = *(const float4*)&Bw[(size_t)(k0 + bkk) * N + n0 + bns];
        }

        #pragma unroll
        for (int kk = 0; kk < 8; kk++) {
            float a[8];
            *(float4*)&a[0] = *(float4*)&As[cur][kk][rm];
            *(float4*)&a[4] = *(float4*)&As[cur][kk][rm + 4];
            float b[JN];
            *(float4*)&b[0] = *(float4*)&Bs[cur][kk][tx * 4];
            if (TN == 128)
                *(float4*)&b[4] = *(float4*)&Bs[cur][kk][64 + tx * 4];
            #pragma unroll
            for (int i = 0; i < 8; i++)
                #pragma unroll
                for (int j = 0; j < JN; j++)
                    acc[i][j] += a[i] * b[j];
        }

        if (has) {
            int nb = 1 - cur;
            As[nb][akseg+0][arow] = av.x; As[nb][akseg+1][arow] = av.y;
            As[nb][akseg+2][arow] = av.z; As[nb][akseg+3][arow] = av.w;
            if (TN == 128 || tid < 128)
                *(float4*)&Bs[nb][bkk][bns] = bv;
        }
        __syncthreads();
    }

    // epilogue: cols n0 + 4tx + j  (and n0 + 64 + 4tx + j for TN=128)
    float bz[JN];
    #pragma unroll
    for (int j = 0; j < 4; j++) bz[j] = bias[n0 + tx * 4 + j];
    if (TN == 128)
        #pragma unroll
        for (int j = 0; j < 4; j++) bz[4 + j] = bias[n0 + 64 + tx * 4 + j];

    #pragma unroll
    for (int i = 0; i < 8; i++) {
        float* crow = &C[(size_t)(m0 + rm + i) * N + n0];
        float4 v0;
        v0.x = acc[i][0] + bz[0]; v0.y = acc[i][1] + bz[1];
        v0.z = acc[i][2] + bz[2]; v0.w = acc[i][3] + bz[3];
        *(float4*)&crow[tx * 4] = v0;
        if (TN == 128) {
            float4 v1;
            v1.x = acc[i][4] + bz[4]; v1.y = acc[i][5] + bz[5];
            v1.z = acc[i][6] + bz[6]; v1.w = acc[i][7] + bz[7];
            *(float4*)&crow[64 + tx * 4] = v1;
        }
    }
}

// ---------------- flash attention v2 (fp32, causal) ----------------
// 128 threads, Q tile 128, K/V tiles 64, 8x8 micro-tile per thread.
// smem: Qs 32KB + Ks 16KB + Vs 16KB + Ps 32KB = 96KB dynamic.
__global__ void __launch_bounds__(128, 2)
flash_attn()
{
    extern __shared__ float sm[];
    float* Qs = sm;                 // [128][64] swizzled: col4 ^= (row>>3)&3
    float* Ks = Qs + 128 * 64;      // [64][64]  swizzled: col4 ^= row&7
    float* Vs = Ks + 64 * 64;       // [64][64]  plain
    float* Ps = Vs + 64 * 64;       // [128][64] swizzled: col4 ^= (row>>3)&3

    const int tid = threadIdx.x;
    const int tx  = tid & 7;        // col group: S cols = tx + 8j
    const int ty  = tid >> 3;       // 0..15, rows r0 = 8*ty
    const int g   = ty & 3;         // swizzle group
    const int r0  = ty * 8;

    const int qt = (int)gridDim.x - 1 - (int)blockIdx.x;  // heavy tiles first
    const int q0 = qt * 128;
    const int bh = blockIdx.y;
    const int b  = bh / Hh;
    const int h  = bh - b * Hh;

    const float* qg = g_c + (size_t)(b * LLen) * N3E + h * Dd;
    const float* kg = qg + Ee;
    const float* vg = qg + 2 * Ee;

    // load Q tile: 128 rows x 16 float4 = 2048 f4 / 128 thr = 16 each
    #pragma unroll
    for (int i = 0; i < 16; i++) {
        int f4 = tid + i * 128;
        int r  = f4 >> 4;
        int c4 = f4 & 15;
        float4 v = *(const float4*)&qg[(size_t)(q0 + r) * N3E + c4 * 4];
        *(float4*)&Qs[r * 64 + ((c4 ^ ((r >> 3) & 3)) << 2)] = v;
    }

    float m[8], l[8], o[8][8];
    #pragma unroll
    for (int i = 0; i < 8; i++) {
        m[i] = -INFINITY; l[i] = 0.f;
        #pragma unroll
        for (int j = 0; j < 8; j++) o[i][j] = 0.f;
    }

    for (int kb = 0; kb <= q0 + 64; kb += 64) {
        // load K/V tile into registers, then smem
        float4 kvK[8], kvV[8];
        #pragma unroll
        for (int i = 0; i < 8; i++) {
            int f4 = tid + i * 128;
            int r  = f4 >> 4;       // 0..63
            int c4 = f4 & 15;
            kvK[i] = *(const float4*)&kg[(size_t)(kb + r) * N3E + c4 * 4];
            kvV[i] = *(const float4*)&vg[(size_t)(kb + r) * N3E + c4 * 4];
        }
        __syncthreads();   // prev iter's PV reads of Vs/Ps done
        #pragma unroll
        for (int i = 0; i < 8; i++) {
            int f4 = tid + i * 128;
            int r  = f4 >> 4;
            int c4 = f4 & 15;
            *(float4*)&Ks[r * 64 + ((c4 ^ (r & 7)) << 2)] = kvK[i];
            *(float4*)&Vs[r * 64 + c4 * 4] = kvV[i];
        }
        __syncthreads();

        // S = Q K^T : 8x8 per thread
        float s[8][8];
        #pragma unroll
        for (int i = 0; i < 8; i++)
            #pragma unroll
            for (int j = 0; j < 8; j++) s[i][j] = 0.f;

        #pragma unroll 4
        for (int dc = 0; dc < 16; dc++) {
            float4 q[8], kr[8];
            #pragma unroll
            for (int i = 0; i < 8; i++)
                q[i] = *(float4*)&Qs[(r0 + i) * 64 + ((dc ^ g) << 2)];
            #pragma unroll
            for (int j = 0; j < 8; j++)
                kr[j] = *(float4*)&Ks[(tx + 8 * j) * 64 + ((dc ^ tx) << 2)];
            #pragma unroll
            for (int i = 0; i < 8; i++)
                #pragma unroll
                for (int j = 0; j < 8; j++) {
                    s[i][j] += q[i].x * kr[j].x;
                    s[i][j] += q[i].y * kr[j].y;
                    s[i][j] += q[i].z * kr[j].z;
                    s[i][j] += q[i].w * kr[j].w;
                }
        }

        // causal mask
        if (kb >= q0) {
            #pragma unroll
            for (int i = 0; i < 8; i++) {
                int row = q0 + r0 + i;
                #pragma unroll
                for (int j = 0; j < 8; j++)
                    if (kb + tx + 8 * j > row) s[i][j] = -1e9f;
            }
        }

        // online softmax: row shared by 8 lanes (xor 1,2,4)
        #pragma unroll
        for (int i = 0; i < 8; i++) {
            float mt = s[i][0];
            #pragma unroll
            for (int j = 1; j < 8; j++) mt = fmaxf(mt, s[i][j]);
            mt = fmaxf(mt, __shfl_xor_sync(0xffffffffu, mt, 1));
            mt = fmaxf(mt, __shfl_xor_sync(0xffffffffu, mt, 2));
            mt = fmaxf(mt, __shfl_xor_sync(0xffffffffu, mt, 4));
            float mn = fmaxf(m[i], mt);
            float sc = __expf(m[i] - mn);
            m[i] = mn;
            float ls = 0.f;
            #pragma unroll
            for (int j = 0; j < 8; j++) {
                s[i][j] = __expf(s[i][j] - mn);
                ls += s[i][j];
            }
            ls += __shfl_xor_sync(0xffffffffu, ls, 1);
            ls += __shfl_xor_sync(0xffffffffu, ls, 2);
            ls += __shfl_xor_sync(0xffffffffu, ls, 4);
            l[i] = l[i] * sc + ls;
            #pragma unroll
            for (int j = 0; j < 8; j++) o[i][j] *= sc;
        }

        // write P (swizzled like Qs)
        #pragma unroll
        for (int i = 0; i < 8; i++)
            #pragma unroll
            for (int j = 0; j < 8; j++) {
                int c = tx + 8 * j;
                Ps[(r0 + i) * 64 + (((c >> 2) ^ g) << 2) + (c & 3)] = s[i][j];
            }
        __syncthreads();

        // O += P V : o cols {4tx+j, 32+4tx+j}
        #pragma unroll 4
        for (int k4 = 0; k4 < 16; k4++) {
            float4 p[8], va[4], vb[4];
            #pragma unroll
            for (int i = 0; i < 8; i++)
                p[i] = *(float4*)&Ps[(r0 + i) * 64 + ((k4 ^ g) << 2)];
            #pragma unroll
            for (int kk = 0; kk < 4; kk++) {
                va[kk] = *(float4*)&Vs[(k4 * 4 + kk) * 64 + tx * 4];
                vb[kk] = *(float4*)&Vs[(k4 * 4 + kk) * 64 + 32 + tx * 4];
            }
            #pragma unroll
            for (int i = 0; i < 8; i++) {
                o[i][0] += p[i].x*va[0].x + p[i].y*va[1].x + p[i].z*va[2].x + p[i].w*va[3].x;
                o[i][1] += p[i].x*va[0].y + p[i].y*va[1].y + p[i].z*va[2].y + p[i].w*va[3].y;
                o[i][2] += p[i].x*va[0].z + p[i].y*va[1].z + p[i].z*va[2].z + p[i].w*va[3].z;
                o[i][3] += p[i].x*va[0].w + p[i].y*va[1].w + p[i].z*va[2].w + p[i].w*va[3].w;
                o[i][4] += p[i].x*vb[0].x + p[i].y*vb[1].x + p[i].z*vb[2].x + p[i].w*vb[3].x;
                o[i][5] += p[i].x*vb[0].y + p[i].y*vb[1].y + p[i].z*vb[2].y + p[i].w*vb[3].y;
                o[i][6] += p[i].x*vb[0].z + p[i].y*vb[1].z + p[i].z*vb[2].z + p[i].w*vb[3].z;
                o[i][7] += p[i].x*vb[0].w + p[i].y*vb[1].w + p[i].z*vb[2].w + p[i].w*vb[3].w;
            }
        }
    }

    // normalize + store
    float* ag = g_a + (size_t)(b * LLen + q0) * Ee + h * Dd;
    #pragma unroll
    for (int i = 0; i < 8; i++) {
        float inv = 1.f / l[i];
        float4 v0, v1;
        v0.x = o[i][0]*inv; v0.y = o[i][1]*inv; v0.z = o[i][2]*inv; v0.w = o[i][3]*inv;
        v1.x = o[i][4]*inv; v1.y = o[i][5]*inv; v1.z = o[i][6]*inv; v1.w = o[i][7]*inv;
        *(float4*)&ag[(size_t)(r0 + i) * Ee + tx * 4] = v0;
        *(float4*)&ag[(size_t)(r0 + i) * Ee + 32 + tx * 4] = v1;
    }
}

// ---------------- launch ----------------
extern "C" void kernel_launch(void* const* d_in, const int* in_sizes, int n_in,
                              void* d_out, int out_size)
{
    const float* x     = (const float*)d_in[0];
    const float* w_in  = (const float*)d_in[1];
    const float* b_in  = (const float*)d_in[2];
    const float* A_in  = (const float*)d_in[3];
    const float* B_in  = (const float*)d_in[4];
    const float* w_out = (const float*)d_in[5];
    const float* b_out = (const float*)d_in[6];
    const float* A_out = (const float*)d_in[7];
    const float* B_out = (const float*)d_in[8];
    float* out = (float*)d_out;

    float *p_w1, *p_w2, *p_c, *p_a;
    cudaGetSymbolAddress((void**)&p_w1, g_w1);
    cudaGetSymbolAddress((void**)&p_w2, g_w2);
    cudaGetSymbolAddress((void**)&p_c,  g_c);
    cudaGetSymbolAddress((void**)&p_a,  g_a);

    static bool attr_set = false;
    if (!attr_set) {
        cudaFuncSetAttribute(flash_attn, cudaFuncAttributeMaxDynamicSharedMemorySize, 98304);
        attr_set = true;
    }

    {
        int total = Ee * N3E;
        prep_w<<<(total + 255) / 256, 256>>>(w_in, A_in, B_in, w_out, A_out, B_out);
    }
    {
        dim3 grid(N3E / 128, Mrows / 128);
        sgemm_bias<128><<<grid, 256>>>(x, p_w1, b_in, p_c, N3E);
    }
    {
        dim3 grid(LLen / 128, Bb * Hh);
        flash_attn<<<grid, 128, 98304>>>();
    }
    {
        dim3 grid(Ee / 64, Mrows / 128);
        sgemm_bias<64><<<grid, 256>>>(p_a, p_w2, b_out, out, Ee);
    }
}

// round 4
// speedup vs baseline: 1.5241x; 1.4109x over previous
#include <cuda_runtime.h>
#include <cstdint>
#include <math.h>

#define Hh 12
#define Ee 768
#define Dd 64
#define LLen 2048
#define Bb 2
#define Mrows (Bb*LLen)      // 4096
#define N3E (3*Ee)           // 2304
#define LORA 8.0f

// ---------------- scratch ----------------
__device__ float g_w1t[N3E * Ee];    // fused LoRA input weights, transposed [2304][768], tf32-rounded
__device__ float g_w2t[Ee * Ee];     // fused LoRA output weights, transposed [768][768], tf32-rounded
__device__ float g_xc [Mrows * Ee];  // tf32-rounded x
__device__ float g_c  [Mrows * N3E]; // qkv activations [4096, 2304]
__device__ float g_a  [Mrows * Ee];  // attention output [4096, 768], tf32-rounded

// =================== helpers ===================
__device__ __forceinline__ uint32_t smem_u32(const void* p) {
    uint32_t a;
    asm("{ .reg .u64 t; cvta.to.shared.u64 t, %1; cvt.u32.u64 %0, t; }" : "=r"(a) : "l"(p));
    return a;
}
__device__ __forceinline__ float rna(float x) {
    uint32_t r;
    asm("cvt.rna.tf32.f32 %0, %1;" : "=r"(r) : "f"(x));
    return __uint_as_float(r);
}
__device__ __forceinline__ void cp16(uint32_t dst, const void* src) {
    asm volatile("cp.async.cg.shared.global [%0], [%1], 16;" :: "r"(dst), "l"(src));
}
#define CP_COMMIT() asm volatile("cp.async.commit_group;" ::: "memory")

__device__ __forceinline__ void ldsm4(uint32_t& r0, uint32_t& r1, uint32_t& r2, uint32_t& r3,
                                      uint32_t addr) {
    asm volatile("ldmatrix.sync.aligned.m8n8.x4.shared.b16 {%0,%1,%2,%3}, [%4];"
                 : "=r"(r0), "=r"(r1), "=r"(r2), "=r"(r3) : "r"(addr));
}
__device__ __forceinline__ void mma_tf32(float* c, uint32_t a0, uint32_t a1, uint32_t a2,
                                         uint32_t a3, uint32_t b0, uint32_t b1) {
    asm volatile("mma.sync.aligned.m16n8k8.row.col.f32.tf32.tf32.f32 "
                 "{%0,%1,%2,%3}, {%4,%5,%6,%7}, {%8,%9}, {%0,%1,%2,%3};"
                 : "+f"(c[0]), "+f"(c[1]), "+f"(c[2]), "+f"(c[3])
                 : "r"(a0), "r"(a1), "r"(a2), "r"(a3), "r"(b0), "r"(b1));
}

// ---------------- prep: wt[o][e] = rna(w[e][o] + 8*(B@A)[e][o]) ----------------
__global__ void prep_wt(const float* __restrict__ w, const float* __restrict__ Aa,
                        const float* __restrict__ Bm, float* __restrict__ wt, int ncols)
{
    __shared__ float t[32][33];
    int o0 = blockIdx.x * 32, e0 = blockIdx.y * 32;
    int tx = threadIdx.x, ty = threadIdx.y;
    #pragma unroll
    for (int r = 0; r < 4; r++) {
        int e = e0 + ty + r * 8, o = o0 + tx;
        float s = 0.f;
        #pragma unroll
        for (int q = 0; q < 4; q++) s += Bm[e*4 + q] * Aa[q*ncols + o];
        t[ty + r*8][tx] = w[(size_t)e * ncols + o] + LORA * s;
    }
    __syncthreads();
    #pragma unroll
    for (int r = 0; r < 4; r++) {
        int o = o0 + ty + r * 8, e = e0 + tx;
        wt[(size_t)o * Ee + e] = rna(t[tx][ty + r*8]);
    }
}

// ---------------- x -> tf32-rounded copy ----------------
__global__ void cvt_x(const float4* __restrict__ in, float4* __restrict__ out)
{
    int i = blockIdx.x * blockDim.x + threadIdx.x;
    float4 v = in[i];
    v.x = rna(v.x); v.y = rna(v.y); v.z = rna(v.z); v.w = rna(v.w);
    out[i] = v;
}

// ---------------- tf32 mma.sync GEMM: C[M,N] = A[M,768] * Wt[N,768]^T + bias ----------------
// CTA 128xTN, ktile 32, 4-stage cp.async, 256 threads (8 warps).
// TN=128: warp tile 64x32 (2Mx4N warps). TN=64: warp tile 32x32 (4Mx2N warps).
#define STG 4
#define NTk 24   // 768/32

template<int TN>
__global__ void __launch_bounds__(256, 1)
gemm_tc(const float* __restrict__ A, const float* __restrict__ Wt,
        const float* __restrict__ bias, float* __restrict__ C, int N)
{
    constexpr int MT = (TN == 128) ? 4 : 2;      // mtiles (16 rows) per warp
    constexpr int WM = 128 / (MT * 16);          // 2 or 4
    constexpr int ABYTES = 16384;                // 128 rows * 128B
    constexpr int BBYTES = TN * 128;

    extern __shared__ float sm[];
    const uint32_t sbase = smem_u32(sm);
    const uint32_t sAb = sbase;
    const uint32_t sBb = sbase + STG * ABYTES;

    const int tid  = threadIdx.x;
    const int wid  = tid >> 5;
    const int lane = tid & 31;
    const int m0 = blockIdx.y * 128;
    const int n0 = blockIdx.x * TN;
    const int wm = wid & (WM - 1);
    const int wn = wid / WM;

    // gmem->smem loader mapping
    const int lrow = tid >> 3;       // 0..31
    const int lc16 = tid & 7;        // chunk

    auto load_tile = [&](int kt) {
        const int st = kt & (STG - 1);
        const uint32_t sA = sAb + st * ABYTES;
        const uint32_t sB = sBb + st * BBYTES;
        const float* Ag = A  + (size_t)m0 * Ee + kt * 32;
        const float* Bg = Wt + (size_t)n0 * Ee + kt * 32;
        #pragma unroll
        for (int i = 0; i < 4; i++) {
            int row = lrow + i * 32;
            uint32_t off = row * 128 + ((lc16 ^ (row & 7)) << 4);
            cp16(sA + off, Ag + (size_t)row * Ee + lc16 * 4);
        }
        #pragma unroll
        for (int i = 0; i < TN / 32; i++) {
            int row = lrow + i * 32;
            uint32_t off = row * 128 + ((lc16 ^ (row & 7)) << 4);
            cp16(sB + off, Bg + (size_t)row * Ee + lc16 * 4);
        }
        CP_COMMIT();
    };

    float acc[MT][4][4];
    #pragma unroll
    for (int i = 0; i < MT; i++)
        #pragma unroll
        for (int j = 0; j < 4; j++)
            #pragma unroll
            for (int k = 0; k < 4; k++) acc[i][j][k] = 0.f;

    // per-lane LDSM row geometry (rows fixed; chunk varies with ks)
    int arow[MT], bro[2];
    #pragma unroll
    for (int mt = 0; mt < MT; mt++) arow[mt] = wm * MT * 16 + mt * 16 + (lane & 15);
    const int achk = (lane >> 4) & 1;
    #pragma unroll
    for (int p = 0; p < 2; p++) bro[p] = wn * 32 + p * 16 + (lane & 7) + ((lane >> 4) & 1) * 8;
    const int bchk = (lane >> 3) & 1;

    #pragma unroll
    for (int kt = 0; kt < STG - 1; kt++) load_tile(kt);

    for (int it = 0; it < NTk; ++it) {
        const int st = it & (STG - 1);
        if (it < NTk - 2)       asm volatile("cp.async.wait_group 2;" ::: "memory");
        else if (it == NTk - 2) asm volatile("cp.async.wait_group 1;" ::: "memory");
        else                    asm volatile("cp.async.wait_group 0;" ::: "memory");
        __syncthreads();

        if (it + STG - 1 < NTk) load_tile(it + STG - 1);

        const uint32_t sA = sAb + st * ABYTES;
        const uint32_t sB = sBb + st * BBYTES;

        #pragma unroll
        for (int ks = 0; ks < 4; ks++) {
            uint32_t af[MT][4];
            #pragma unroll
            for (int mt = 0; mt < MT; mt++) {
                uint32_t addr = sA + arow[mt] * 128 + (((2*ks + achk) ^ (arow[mt] & 7)) << 4);
                ldsm4(af[mt][0], af[mt][1], af[mt][2], af[mt][3], addr);
            }
            uint32_t bf[4][2];
            #pragma unroll
            for (int p = 0; p < 2; p++) {
                uint32_t addr = sB + bro[p] * 128 + (((2*ks + bchk) ^ (bro[p] & 7)) << 4);
                ldsm4(bf[2*p][0], bf[2*p][1], bf[2*p+1][0], bf[2*p+1][1], addr);
            }
            #pragma unroll
            for (int mt = 0; mt < MT; mt++)
                #pragma unroll
                for (int nt = 0; nt < 4; nt++)
                    mma_tf32(acc[mt][nt], af[mt][0], af[mt][1], af[mt][2], af[mt][3],
                             bf[nt][0], bf[nt][1]);
        }
        __syncthreads();
    }

    // epilogue
    const int g = lane >> 2, t = lane & 3;
    #pragma unroll
    for (int nt = 0; nt < 4; nt++) {
        const int col = n0 + wn * 32 + nt * 8 + 2 * t;
        float2 bz = *(const float2*)&bias[col];
        #pragma unroll
        for (int mt = 0; mt < MT; mt++) {
            const int r0 = m0 + wm * MT * 16 + mt * 16 + g;
            float2 v0, v1;
            v0.x = acc[mt][nt][0] + bz.x; v0.y = acc[mt][nt][1] + bz.y;
            v1.x = acc[mt][nt][2] + bz.x; v1.y = acc[mt][nt][3] + bz.y;
            *(float2*)&C[(size_t)r0 * N + col]       = v0;
            *(float2*)&C[(size_t)(r0 + 8) * N + col] = v1;
        }
    }
}

// ---------------- flash attention (fp32, causal); stores tf32-rounded output ----------------
__global__ void __launch_bounds__(128, 2)
flash_attn()
{
    extern __shared__ float smf[];
    float* Qs = smf;
    float* Ks = Qs + 128 * 64;
    float* Vs = Ks + 64 * 64;
    float* Ps = Vs + 64 * 64;

    const int tid = threadIdx.x;
    const int tx  = tid & 7;
    const int ty  = tid >> 3;
    const int g   = ty & 3;
    const int r0  = ty * 8;

    const int qt = (int)gridDim.x - 1 - (int)blockIdx.x;
    const int q0 = qt * 128;
    const int bh = blockIdx.y;
    const int b  = bh / Hh;
    const int h  = bh - b * Hh;

    const float* qg = g_c + (size_t)(b * LLen) * N3E + h * Dd;
    const float* kg = qg + Ee;
    const float* vg = qg + 2 * Ee;

    #pragma unroll
    for (int i = 0; i < 16; i++) {
        int f4 = tid + i * 128;
        int r  = f4 >> 4;
        int c4 = f4 & 15;
        float4 v = *(const float4*)&qg[(size_t)(q0 + r) * N3E + c4 * 4];
        *(float4*)&Qs[r * 64 + ((c4 ^ ((r >> 3) & 3)) << 2)] = v;
    }

    float m[8], l[8], o[8][8];
    #pragma unroll
    for (int i = 0; i < 8; i++) {
        m[i] = -INFINITY; l[i] = 0.f;
        #pragma unroll
        for (int j = 0; j < 8; j++) o[i][j] = 0.f;
    }

    for (int kb = 0; kb <= q0 + 64; kb += 64) {
        float4 kvK[8], kvV[8];
        #pragma unroll
        for (int i = 0; i < 8; i++) {
            int f4 = tid + i * 128;
            int r  = f4 >> 4;
            int c4 = f4 & 15;
            kvK[i] = *(const float4*)&kg[(size_t)(kb + r) * N3E + c4 * 4];
            kvV[i] = *(const float4*)&vg[(size_t)(kb + r) * N3E + c4 * 4];
        }
        __syncthreads();
        #pragma unroll
        for (int i = 0; i < 8; i++) {
            int f4 = tid + i * 128;
            int r  = f4 >> 4;
            int c4 = f4 & 15;
            *(float4*)&Ks[r * 64 + ((c4 ^ (r & 7)) << 2)] = kvK[i];
            *(float4*)&Vs[r * 64 + c4 * 4] = kvV[i];
        }
        __syncthreads();

        float s[8][8];
        #pragma unroll
        for (int i = 0; i < 8; i++)
            #pragma unroll
            for (int j = 0; j < 8; j++) s[i][j] = 0.f;

        #pragma unroll 4
        for (int dc = 0; dc < 16; dc++) {
            float4 q[8], kr[8];
            #pragma unroll
            for (int i = 0; i < 8; i++)
                q[i] = *(float4*)&Qs[(r0 + i) * 64 + ((dc ^ g) << 2)];
            #pragma unroll
            for (int j = 0; j < 8; j++)
                kr[j] = *(float4*)&Ks[(tx + 8 * j) * 64 + ((dc ^ tx) << 2)];
            #pragma unroll
            for (int i = 0; i < 8; i++)
                #pragma unroll
                for (int j = 0; j < 8; j++) {
                    s[i][j] += q[i].x * kr[j].x;
                    s[i][j] += q[i].y * kr[j].y;
                    s[i][j] += q[i].z * kr[j].z;
                    s[i][j] += q[i].w * kr[j].w;
                }
        }

        if (kb >= q0) {
            #pragma unroll
            for (int i = 0; i < 8; i++) {
                int row = q0 + r0 + i;
                #pragma unroll
                for (int j = 0; j < 8; j++)
                    if (kb + tx + 8 * j > row) s[i][j] = -1e9f;
            }
        }

        #pragma unroll
        for (int i = 0; i < 8; i++) {
            float mt = s[i][0];
            #pragma unroll
            for (int j = 1; j < 8; j++) mt = fmaxf(mt, s[i][j]);
            mt = fmaxf(mt, __shfl_xor_sync(0xffffffffu, mt, 1));
            mt = fmaxf(mt, __shfl_xor_sync(0xffffffffu, mt, 2));
            mt = fmaxf(mt, __shfl_xor_sync(0xffffffffu, mt, 4));
            float mn = fmaxf(m[i], mt);
            float sc = __expf(m[i] - mn);
            m[i] = mn;
            float ls = 0.f;
            #pragma unroll
            for (int j = 0; j < 8; j++) {
                s[i][j] = __expf(s[i][j] - mn);
                ls += s[i][j];
            }
            ls += __shfl_xor_sync(0xffffffffu, ls, 1);
            ls += __shfl_xor_sync(0xffffffffu, ls, 2);
            ls += __shfl_xor_sync(0xffffffffu, ls, 4);
            l[i] = l[i] * sc + ls;
            #pragma unroll
            for (int j = 0; j < 8; j++) o[i][j] *= sc;
        }

        #pragma unroll
        for (int i = 0; i < 8; i++)
            #pragma unroll
            for (int j = 0; j < 8; j++) {
                int c = tx + 8 * j;
                Ps[(r0 + i) * 64 + (((c >> 2) ^ g) << 2) + (c & 3)] = s[i][j];
            }
        __syncthreads();

        #pragma unroll 4
        for (int k4 = 0; k4 < 16; k4++) {
            float4 p[8], va[4], vb[4];
            #pragma unroll
            for (int i = 0; i < 8; i++)
                p[i] = *(float4*)&Ps[(r0 + i) * 64 + ((k4 ^ g) << 2)];
            #pragma unroll
            for (int kk = 0; kk < 4; kk++) {
                va[kk] = *(float4*)&Vs[(k4 * 4 + kk) * 64 + tx * 4];
                vb[kk] = *(float4*)&Vs[(k4 * 4 + kk) * 64 + 32 + tx * 4];
            }
            #pragma unroll
            for (int i = 0; i < 8; i++) {
                o[i][0] += p[i].x*va[0].x + p[i].y*va[1].x + p[i].z*va[2].x + p[i].w*va[3].x;
                o[i][1] += p[i].x*va[0].y + p[i].y*va[1].y + p[i].z*va[2].y + p[i].w*va[3].y;
                o[i][2] += p[i].x*va[0].z + p[i].y*va[1].z + p[i].z*va[2].z + p[i].w*va[3].z;
                o[i][3] += p[i].x*va[0].w + p[i].y*va[1].w + p[i].z*va[2].w + p[i].w*va[3].w;
                o[i][4] += p[i].x*vb[0].x + p[i].y*vb[1].x + p[i].z*vb[2].x + p[i].w*vb[3].x;
                o[i][5] += p[i].x*vb[0].y + p[i].y*vb[1].y + p[i].z*vb[2].y + p[i].w*vb[3].y;
                o[i][6] += p[i].x*vb[0].z + p[i].y*vb[1].z + p[i].z*vb[2].z + p[i].w*vb[3].z;
                o[i][7] += p[i].x*vb[0].w + p[i].y*vb[1].w + p[i].z*vb[2].w + p[i].w*vb[3].w;
            }
        }
    }

    float* ag = g_a + (size_t)(b * LLen + q0) * Ee + h * Dd;
    #pragma unroll
    for (int i = 0; i < 8; i++) {
        float inv = 1.f / l[i];
        float4 v0, v1;
        v0.x = rna(o[i][0]*inv); v0.y = rna(o[i][1]*inv);
        v0.z = rna(o[i][2]*inv); v0.w = rna(o[i][3]*inv);
        v1.x = rna(o[i][4]*inv); v1.y = rna(o[i][5]*inv);
        v1.z = rna(o[i][6]*inv); v1.w = rna(o[i][7]*inv);
        *(float4*)&ag[(size_t)(r0 + i) * Ee + tx * 4] = v0;
        *(float4*)&ag[(size_t)(r0 + i) * Ee + 32 + tx * 4] = v1;
    }
}

// ---------------- launch ----------------
extern "C" void kernel_launch(void* const* d_in, const int* in_sizes, int n_in,
                              void* d_out, int out_size)
{
    const float* x     = (const float*)d_in[0];
    const float* w_in  = (const float*)d_in[1];
    const float* b_in  = (const float*)d_in[2];
    const float* A_in  = (const float*)d_in[3];
    const float* B_in  = (const float*)d_in[4];
    const float* w_out = (const float*)d_in[5];
    const float* b_out = (const float*)d_in[6];
    const float* A_out = (const float*)d_in[7];
    const float* B_out = (const float*)d_in[8];
    float* out = (float*)d_out;

    float *p_w1t, *p_w2t, *p_xc, *p_c, *p_a;
    cudaGetSymbolAddress((void**)&p_w1t, g_w1t);
    cudaGetSymbolAddress((void**)&p_w2t, g_w2t);
    cudaGetSymbolAddress((void**)&p_xc,  g_xc);
    cudaGetSymbolAddress((void**)&p_c,   g_c);
    cudaGetSymbolAddress((void**)&p_a,   g_a);

    const int smem1 = STG * (16384 + 128 * 128);  // 4*(16K+16K) = 128KB
    const int smem2 = STG * (16384 + 64 * 128);   // 4*(16K+8K)  = 96KB
    cudaFuncSetAttribute(gemm_tc<128>, cudaFuncAttributeMaxDynamicSharedMemorySize, smem1);
    cudaFuncSetAttribute(gemm_tc<64>,  cudaFuncAttributeMaxDynamicSharedMemorySize, smem2);
    cudaFuncSetAttribute(flash_attn, cudaFuncAttributeMaxDynamicSharedMemorySize, 98304);

    // 1) weight prep (LoRA fuse + transpose + tf32 round), x rounding
    {
        dim3 blk(32, 8);
        dim3 g1(N3E / 32, Ee / 32);
        prep_wt<<<g1, blk>>>(w_in, A_in, B_in, p_w1t, N3E);
        dim3 g2(Ee / 32, Ee / 32);
        prep_wt<<<g2, blk>>>(w_out, A_out, B_out, p_w2t, Ee);
        cvt_x<<<Mrows * Ee / 4 / 256, 256>>>((const float4*)x, (float4*)p_xc);
    }
    // 2) QKV projection (tensor cores, tf32 mma.sync)
    {
        dim3 grid(N3E / 128, Mrows / 128);
        gemm_tc<128><<<grid, 256, smem1>>>(p_xc, p_w1t, b_in, p_c, N3E);
    }
    // 3) causal attention (fp32 SIMT)
    {
        dim3 grid(LLen / 128, Bb * Hh);
        flash_attn<<<grid, 128, 98304>>>();
    }
    // 4) output projection (tensor cores, tf32 mma.sync)
    {
        dim3 grid(Ee / 64, Mrows / 128);
        gemm_tc<64><<<grid, 256, smem2>>>(p_a, p_w2t, b_out, out, Ee);
    }
}

// round 6
// speedup vs baseline: 1.6278x; 1.0680x over previous
#include <cuda_runtime.h>
#include <cstdint>
#include <math.h>

#define Hh 12
#define Ee 768
#define Dd 64
#define LLen 2048
#define Bb 2
#define Mrows (Bb*LLen)      // 4096
#define N3E (3*Ee)           // 2304
#define LORA 8.0f

// ---------------- scratch ----------------
__device__ float g_w1h[N3E * Ee], g_w1l[N3E * Ee];   // fused input weights^T hi/lo
__device__ float g_w2h[Ee * Ee],  g_w2l[Ee * Ee];    // fused output weights^T hi/lo
__device__ float g_xh [Mrows * Ee], g_xl [Mrows * Ee];
__device__ float g_c  [Mrows * N3E];                 // qkv activations (fp32)
__device__ float g_ah [Mrows * Ee], g_al [Mrows * Ee]; // attention out hi/lo

// =================== helpers ===================
__device__ __forceinline__ uint32_t smem_u32(const void* p) {
    uint32_t a;
    asm("{ .reg .u64 t; cvta.to.shared.u64 t, %1; cvt.u32.u64 %0, t; }" : "=r"(a) : "l"(p));
    return a;
}
__device__ __forceinline__ float rna(float x) {
    uint32_t r;
    asm("cvt.rna.tf32.f32 %0, %1;" : "=r"(r) : "f"(x));
    return __uint_as_float(r);
}
__device__ __forceinline__ void cp16(uint32_t dst, const void* src) {
    asm volatile("cp.async.cg.shared.global [%0], [%1], 16;" :: "r"(dst), "l"(src));
}
#define CP_COMMIT() asm volatile("cp.async.commit_group;" ::: "memory")

__device__ __forceinline__ void ldsm4(uint32_t& r0, uint32_t& r1, uint32_t& r2, uint32_t& r3,
                                      uint32_t addr) {
    asm volatile("ldmatrix.sync.aligned.m8n8.x4.shared.b16 {%0,%1,%2,%3}, [%4];"
                 : "=r"(r0), "=r"(r1), "=r"(r2), "=r"(r3) : "r"(addr));
}
__device__ __forceinline__ void mma_tf32(float* c, uint32_t a0, uint32_t a1, uint32_t a2,
                                         uint32_t a3, uint32_t b0, uint32_t b1) {
    asm volatile("mma.sync.aligned.m16n8k8.row.col.f32.tf32.tf32.f32 "
                 "{%0,%1,%2,%3}, {%4,%5,%6,%7}, {%8,%9}, {%0,%1,%2,%3};"
                 : "+f"(c[0]), "+f"(c[1]), "+f"(c[2]), "+f"(c[3])
                 : "r"(a0), "r"(a1), "r"(a2), "r"(a3), "r"(b0), "r"(b1));
}

// ---------------- prep: wt = (w + 8*B@A)^T split into tf32 hi/lo ----------------
__global__ void prep_wt(const float* __restrict__ w, const float* __restrict__ Aa,
                        const float* __restrict__ Bm, float* __restrict__ wh,
                        float* __restrict__ wl, int ncols)
{
    __shared__ float t[32][33];
    int o0 = blockIdx.x * 32, e0 = blockIdx.y * 32;
    int tx = threadIdx.x, ty = threadIdx.y;
    #pragma unroll
    for (int r = 0; r < 4; r++) {
        int e = e0 + ty + r * 8, o = o0 + tx;
        float s = 0.f;
        #pragma unroll
        for (int q = 0; q < 4; q++) s += Bm[e*4 + q] * Aa[q*ncols + o];
        t[ty + r*8][tx] = w[(size_t)e * ncols + o] + LORA * s;
    }
    __syncthreads();
    #pragma unroll
    for (int r = 0; r < 4; r++) {
        int o = o0 + ty + r * 8, e = e0 + tx;
        float f = t[tx][ty + r*8];
        float hf = rna(f);
        wh[(size_t)o * Ee + e] = hf;
        wl[(size_t)o * Ee + e] = rna(f - hf);
    }
}

// ---------------- x -> tf32 hi/lo split ----------------
__global__ void cvt_x(const float4* __restrict__ in, float4* __restrict__ oh,
                      float4* __restrict__ ol)
{
    int i = blockIdx.x * blockDim.x + threadIdx.x;
    float4 v = in[i];
    float4 h, l;
    h.x = rna(v.x); l.x = rna(v.x - h.x);
    h.y = rna(v.y); l.y = rna(v.y - h.y);
    h.z = rna(v.z); l.z = rna(v.z - h.z);
    h.w = rna(v.w); l.w = rna(v.w - h.w);
    oh[i] = h; ol[i] = l;
}

// ---------------- tf32x2 mma.sync GEMM: C = A*Wt^T + bias (3-term compensated) ----------------
#define NTk 24   // 768/32

template<int TN>
__global__ void __launch_bounds__(256, 1)
gemm_tc(const float* __restrict__ Ah, const float* __restrict__ Al,
        const float* __restrict__ Wh, const float* __restrict__ Wl,
        const float* __restrict__ bias, float* __restrict__ C, int N)
{
    constexpr int MT = (TN == 128) ? 4 : 2;
    constexpr int WM = 128 / (MT * 16);
    constexpr int ABYTES = 16384;           // 128 rows x 128B
    constexpr int BBYTES = TN * 128;
    constexpr int SBYTES = 2 * (ABYTES + BBYTES);
    constexpr int STG = (TN == 128) ? 3 : 4;

    extern __shared__ float sm[];
    const uint32_t sbase = smem_u32(sm);

    const int tid  = threadIdx.x;
    const int wid  = tid >> 5;
    const int lane = tid & 31;
    const int m0 = blockIdx.y * 128;
    const int n0 = blockIdx.x * TN;
    const int wm = wid & (WM - 1);
    const int wn = wid / WM;

    const int lrow = tid >> 3;
    const int lc16 = tid & 7;

    auto load_tile = [&](int kt) {
        const int st = kt % STG;
        const uint32_t sAh = sbase + st * SBYTES;
        const uint32_t sAl = sAh + ABYTES;
        const uint32_t sBh = sAl + ABYTES;
        const uint32_t sBl = sBh + BBYTES;
        const float* Agh = Ah + (size_t)m0 * Ee + kt * 32;
        const float* Agl = Al + (size_t)m0 * Ee + kt * 32;
        const float* Bgh = Wh + (size_t)n0 * Ee + kt * 32;
        const float* Bgl = Wl + (size_t)n0 * Ee + kt * 32;
        #pragma unroll
        for (int i = 0; i < 4; i++) {
            int row = lrow + i * 32;
            uint32_t off = row * 128 + ((lc16 ^ (row & 7)) << 4);
            cp16(sAh + off, Agh + (size_t)row * Ee + lc16 * 4);
            cp16(sAl + off, Agl + (size_t)row * Ee + lc16 * 4);
        }
        #pragma unroll
        for (int i = 0; i < TN / 32; i++) {
            int row = lrow + i * 32;
            uint32_t off = row * 128 + ((lc16 ^ (row & 7)) << 4);
            cp16(sBh + off, Bgh + (size_t)row * Ee + lc16 * 4);
            cp16(sBl + off, Bgl + (size_t)row * Ee + lc16 * 4);
        }
        CP_COMMIT();
    };

    float acc[MT][4][4];
    #pragma unroll
    for (int i = 0; i < MT; i++)
        #pragma unroll
        for (int j = 0; j < 4; j++)
            #pragma unroll
            for (int k = 0; k < 4; k++) acc[i][j][k] = 0.f;

    int arow[MT], bro[2];
    #pragma unroll
    for (int mt = 0; mt < MT; mt++) arow[mt] = wm * MT * 16 + mt * 16 + (lane & 15);
    const int achk = (lane >> 4) & 1;
    #pragma unroll
    for (int p = 0; p < 2; p++) bro[p] = wn * 32 + p * 16 + (lane & 7) + ((lane >> 4) & 1) * 8;
    const int bchk = (lane >> 3) & 1;

    #pragma unroll
    for (int kt = 0; kt < STG - 1; kt++) load_tile(kt);

    for (int it = 0; it < NTk; ++it) {
        const int st = it % STG;
        if (STG == 3) {
            if (it < NTk - 1) asm volatile("cp.async.wait_group 1;" ::: "memory");
            else              asm volatile("cp.async.wait_group 0;" ::: "memory");
        } else {
            if (it < NTk - 2)       asm volatile("cp.async.wait_group 2;" ::: "memory");
            else if (it == NTk - 2) asm volatile("cp.async.wait_group 1;" ::: "memory");
            else                    asm volatile("cp.async.wait_group 0;" ::: "memory");
        }
        __syncthreads();

        if (it + STG - 1 < NTk) load_tile(it + STG - 1);

        const uint32_t sAh = sbase + st * SBYTES;
        const uint32_t sAl = sAh + ABYTES;
        const uint32_t sBh = sAl + ABYTES;
        const uint32_t sBl = sBh + BBYTES;

        #pragma unroll
        for (int ks = 0; ks < 4; ks++) {
            uint32_t afh[MT][4];
            #pragma unroll
            for (int mt = 0; mt < MT; mt++)
                ldsm4(afh[mt][0], afh[mt][1], afh[mt][2], afh[mt][3],
                      sAh + arow[mt] * 128 + (((2*ks + achk) ^ (arow[mt] & 7)) << 4));
            uint32_t bfh[4][2];
            #pragma unroll
            for (int p = 0; p < 2; p++)
                ldsm4(bfh[2*p][0], bfh[2*p][1], bfh[2*p+1][0], bfh[2*p+1][1],
                      sBh + bro[p] * 128 + (((2*ks + bchk) ^ (bro[p] & 7)) << 4));
            #pragma unroll
            for (int mt = 0; mt < MT; mt++)
                #pragma unroll
                for (int nt = 0; nt < 4; nt++)
                    mma_tf32(acc[mt][nt], afh[mt][0], afh[mt][1], afh[mt][2], afh[mt][3],
                             bfh[nt][0], bfh[nt][1]);
            uint32_t bfl[4][2];
            #pragma unroll
            for (int p = 0; p < 2; p++)
                ldsm4(bfl[2*p][0], bfl[2*p][1], bfl[2*p+1][0], bfl[2*p+1][1],
                      sBl + bro[p] * 128 + (((2*ks + bchk) ^ (bro[p] & 7)) << 4));
            #pragma unroll
            for (int mt = 0; mt < MT; mt++)
                #pragma unroll
                for (int nt = 0; nt < 4; nt++)
                    mma_tf32(acc[mt][nt], afh[mt][0], afh[mt][1], afh[mt][2], afh[mt][3],
                             bfl[nt][0], bfl[nt][1]);
            uint32_t afl[MT][4];
            #pragma unroll
            for (int mt = 0; mt < MT; mt++)
                ldsm4(afl[mt][0], afl[mt][1], afl[mt][2], afl[mt][3],
                      sAl + arow[mt] * 128 + (((2*ks + achk) ^ (arow[mt] & 7)) << 4));
            #pragma unroll
            for (int mt = 0; mt < MT; mt++)
                #pragma unroll
                for (int nt = 0; nt < 4; nt++)
                    mma_tf32(acc[mt][nt], afl[mt][0], afl[mt][1], afl[mt][2], afl[mt][3],
                             bfh[nt][0], bfh[nt][1]);
        }
        __syncthreads();
    }

    const int g = lane >> 2, t = lane & 3;
    #pragma unroll
    for (int nt = 0; nt < 4; nt++) {
        const int col = n0 + wn * 32 + nt * 8 + 2 * t;
        float2 bz = *(const float2*)&bias[col];
        #pragma unroll
        for (int mt = 0; mt < MT; mt++) {
            const int r0 = m0 + wm * MT * 16 + mt * 16 + g;
            float2 v0, v1;
            v0.x = acc[mt][nt][0] + bz.x; v0.y = acc[mt][nt][1] + bz.y;
            v1.x = acc[mt][nt][2] + bz.x; v1.y = acc[mt][nt][3] + bz.y;
            *(float2*)&C[(size_t)r0 * N + col]       = v0;
            *(float2*)&C[(size_t)(r0 + 8) * N + col] = v1;
        }
    }
}

// ---------------- flash attention: tf32 mma.sync, causal ----------------
// 256 thr (8 warps). Q tile 128, KV tile 64. Warp w owns Q rows 16w..16w+15.
// smem: Qs[128][64], Ks[64][64], Vt[64][64] (V transposed), Ps[128][64]; 96KB.
// swizzle: float4-chunk c' = c ^ ((row&7)<<1), 256B rows.
#define QOFF 0u
#define KOFF (128u * 256u)
#define VOFF (KOFF + 64u * 256u)
#define POFF (VOFF + 64u * 256u)

__global__ void __launch_bounds__(256, 2)
flash_tc()
{
    extern __shared__ float smf[];
    char* smb = (char*)smf;                 // generic base for stores
    const uint32_t QsB = smem_u32(smf);     // shared-space base for ldmatrix
    const uint32_t KsB = QsB + KOFF;
    const uint32_t VtB = QsB + VOFF;
    const uint32_t PsB = QsB + POFF;

    const int tid  = threadIdx.x;
    const int wid  = tid >> 5;
    const int lane = tid & 31;
    const int g = lane >> 2, t = lane & 3;

    const int qt = (int)gridDim.x - 1 - (int)blockIdx.x;
    const int q0 = qt * 128;
    const int bh = blockIdx.y;
    const int b  = bh / Hh;
    const int h  = bh - b * Hh;

    const float* qg = g_c + (size_t)(b * LLen) * N3E + h * Dd;
    const float* kg = qg + Ee;
    const float* vg = qg + 2 * Ee;

    // load Q (rna-rounded): 128 rows x 16 chunks = 2048 f4 / 256 thr = 8 each
    #pragma unroll
    for (int i = 0; i < 8; i++) {
        int f = tid + i * 256;
        int r = f >> 4, c4 = f & 15;
        float4 v = *(const float4*)&qg[(size_t)(q0 + r) * N3E + c4 * 4];
        v.x = rna(v.x); v.y = rna(v.y); v.z = rna(v.z); v.w = rna(v.w);
        *(float4*)(smb + QOFF + r * 256 + ((c4 ^ ((r & 7) << 1)) << 4)) = v;
    }

    float m[2] = {-INFINITY, -INFINITY};
    float l[2] = {0.f, 0.f};
    float oacc[8][4];
    #pragma unroll
    for (int j = 0; j < 8; j++)
        #pragma unroll
        for (int k = 0; k < 4; k++) oacc[j][k] = 0.f;

    const int arow = (wid << 4) + (lane & 15);
    const int achk = (lane >> 4) & 1;
    const int asw  = (arow & 7) << 1;
    int brow[4];
    #pragma unroll
    for (int p = 0; p < 4; p++) brow[p] = (p << 4) + (lane & 7) + (((lane >> 4) & 1) << 3);
    const int bchk = (lane >> 3) & 1;

    const int ntile = 2 * qt + 2;
    for (int ti = 0; ti < ntile; ti++) {
        const int kb = ti * 64;
        // stage K,V in regs: 64 rows x 16 chunks = 1024 f4 / 256 = 4 each
        float4 kr[4], vr[4];
        #pragma unroll
        for (int i = 0; i < 4; i++) {
            int f = tid + i * 256;
            int r = f >> 4, c4 = f & 15;
            kr[i] = *(const float4*)&kg[(size_t)(kb + r) * N3E + c4 * 4];
            vr[i] = *(const float4*)&vg[(size_t)(kb + r) * N3E + c4 * 4];
        }
        __syncthreads();   // prior tile's Ks/Vt reads complete
        #pragma unroll
        for (int i = 0; i < 4; i++) {
            int f = tid + i * 256;
            int r = f >> 4, c4 = f & 15;
            float4 kv = kr[i];
            kv.x = rna(kv.x); kv.y = rna(kv.y); kv.z = rna(kv.z); kv.w = rna(kv.w);
            *(float4*)(smb + KOFF + r * 256 + ((c4 ^ ((r & 7) << 1)) << 4)) = kv;
            // V transpose: Vt[d][key]
            float vv[4] = {rna(vr[i].x), rna(vr[i].y), rna(vr[i].z), rna(vr[i].w)};
            #pragma unroll
            for (int dd = 0; dd < 4; dd++) {
                int drow = c4 * 4 + dd;
                *(float*)(smb + VOFF + drow * 256
                          + (((r >> 2) ^ ((drow & 7) << 1)) << 4) + (r & 3) * 4) = vv[dd];
            }
        }
        __syncthreads();

        // ---- S = Q K^T ----
        float sacc[8][4];
        #pragma unroll
        for (int j = 0; j < 8; j++)
            #pragma unroll
            for (int k = 0; k < 4; k++) sacc[j][k] = 0.f;

        #pragma unroll
        for (int ks = 0; ks < 8; ks++) {
            uint32_t a0, a1, a2, a3;
            ldsm4(a0, a1, a2, a3,
                  QsB + arow * 256 + ((((ks << 1) + achk) ^ asw) << 4));
            uint32_t bf[8][2];
            #pragma unroll
            for (int p = 0; p < 4; p++)
                ldsm4(bf[2*p][0], bf[2*p][1], bf[2*p+1][0], bf[2*p+1][1],
                      KsB + brow[p] * 256 + ((((ks << 1) + bchk) ^ ((brow[p] & 7) << 1)) << 4));
            #pragma unroll
            for (int j = 0; j < 8; j++)
                mma_tf32(sacc[j], a0, a1, a2, a3, bf[j][0], bf[j][1]);
        }

        // causal mask (diagonal tiles)
        if (kb >= q0) {
            const int r0g = q0 + (wid << 4) + g;
            #pragma unroll
            for (int j = 0; j < 8; j++) {
                int cg = kb + (j << 3) + (t << 1);
                if (cg > r0g)         sacc[j][0] = -1e9f;
                if (cg + 1 > r0g)     sacc[j][1] = -1e9f;
                if (cg > r0g + 8)     sacc[j][2] = -1e9f;
                if (cg + 1 > r0g + 8) sacc[j][3] = -1e9f;
            }
        }

        // ---- online softmax (rows g and g+8) ----
        float mt0 = -INFINITY, mt1 = -INFINITY;
        #pragma unroll
        for (int j = 0; j < 8; j++) {
            mt0 = fmaxf(mt0, fmaxf(sacc[j][0], sacc[j][1]));
            mt1 = fmaxf(mt1, fmaxf(sacc[j][2], sacc[j][3]));
        }
        mt0 = fmaxf(mt0, __shfl_xor_sync(0xffffffffu, mt0, 1));
        mt0 = fmaxf(mt0, __shfl_xor_sync(0xffffffffu, mt0, 2));
        mt1 = fmaxf(mt1, __shfl_xor_sync(0xffffffffu, mt1, 1));
        mt1 = fmaxf(mt1, __shfl_xor_sync(0xffffffffu, mt1, 2));
        float mn0 = fmaxf(m[0], mt0), mn1 = fmaxf(m[1], mt1);
        float sc0 = __expf(m[0] - mn0), sc1 = __expf(m[1] - mn1);
        m[0] = mn0; m[1] = mn1;
        float ls0 = 0.f, ls1 = 0.f;
        #pragma unroll
        for (int j = 0; j < 8; j++) {
            sacc[j][0] = __expf(sacc[j][0] - mn0); ls0 += sacc[j][0];
            sacc[j][1] = __expf(sacc[j][1] - mn0); ls0 += sacc[j][1];
            sacc[j][2] = __expf(sacc[j][2] - mn1); ls1 += sacc[j][2];
            sacc[j][3] = __expf(sacc[j][3] - mn1); ls1 += sacc[j][3];
        }
        ls0 += __shfl_xor_sync(0xffffffffu, ls0, 1);
        ls0 += __shfl_xor_sync(0xffffffffu, ls0, 2);
        ls1 += __shfl_xor_sync(0xffffffffu, ls1, 1);
        ls1 += __shfl_xor_sync(0xffffffffu, ls1, 2);
        l[0] = l[0] * sc0 + ls0;
        l[1] = l[1] * sc1 + ls1;
        #pragma unroll
        for (int j = 0; j < 8; j++) {
            oacc[j][0] *= sc0; oacc[j][1] *= sc0;
            oacc[j][2] *= sc1; oacc[j][3] *= sc1;
        }

        // ---- write P (rna) to warp-private smem rows ----
        const int pr0 = (wid << 4) + g;
        const int pr1 = pr0 + 8;
        #pragma unroll
        for (int j = 0; j < 8; j++) {
            int col = (j << 3) + (t << 1);
            int cc  = col >> 2, co = col & 3;
            float2 p0 = make_float2(rna(sacc[j][0]), rna(sacc[j][1]));
            float2 p1 = make_float2(rna(sacc[j][2]), rna(sacc[j][3]));
            *(float2*)(smb + POFF + pr0 * 256 + ((cc ^ ((pr0 & 7) << 1)) << 4) + co * 4) = p0;
            *(float2*)(smb + POFF + pr1 * 256 + ((cc ^ ((pr1 & 7) << 1)) << 4) + co * 4) = p1;
        }
        __syncwarp();

        // ---- O += P V ----
        #pragma unroll
        for (int ks = 0; ks < 8; ks++) {
            uint32_t a0, a1, a2, a3;
            ldsm4(a0, a1, a2, a3,
                  PsB + arow * 256 + ((((ks << 1) + achk) ^ asw) << 4));
            uint32_t vf[8][2];
            #pragma unroll
            for (int p = 0; p < 4; p++)
                ldsm4(vf[2*p][0], vf[2*p][1], vf[2*p+1][0], vf[2*p+1][1],
                      VtB + brow[p] * 256 + ((((ks << 1) + bchk) ^ ((brow[p] & 7) << 1)) << 4));
            #pragma unroll
            for (int j = 0; j < 8; j++)
                mma_tf32(oacc[j], a0, a1, a2, a3, vf[j][0], vf[j][1]);
        }
    }

    // ---- epilogue: normalize, split hi/lo, store ----
    const float inv0 = 1.f / l[0], inv1 = 1.f / l[1];
    const int grow = b * LLen + q0 + (wid << 4) + g;
    float* ah0 = g_ah + (size_t)grow * Ee + h * Dd;
    float* al0 = g_al + (size_t)grow * Ee + h * Dd;
    float* ah1 = ah0 + 8 * Ee;
    float* al1 = al0 + 8 * Ee;
    #pragma unroll
    for (int j = 0; j < 8; j++) {
        int d = (j << 3) + (t << 1);
        float o0 = oacc[j][0] * inv0, o1 = oacc[j][1] * inv0;
        float o2 = oacc[j][2] * inv1, o3 = oacc[j][3] * inv1;
        float h0 = rna(o0), h1 = rna(o1), h2 = rna(o2), h3 = rna(o3);
        *(float2*)&ah0[d] = make_float2(h0, h1);
        *(float2*)&al0[d] = make_float2(rna(o0 - h0), rna(o1 - h1));
        *(float2*)&ah1[d] = make_float2(h2, h3);
        *(float2*)&al1[d] = make_float2(rna(o2 - h2), rna(o3 - h3));
    }
}

// ---------------- launch ----------------
extern "C" void kernel_launch(void* const* d_in, const int* in_sizes, int n_in,
                              void* d_out, int out_size)
{
    const float* x     = (const float*)d_in[0];
    const float* w_in  = (const float*)d_in[1];
    const float* b_in  = (const float*)d_in[2];
    const float* A_in  = (const float*)d_in[3];
    const float* B_in  = (const float*)d_in[4];
    const float* w_out = (const float*)d_in[5];
    const float* b_out = (const float*)d_in[6];
    const float* A_out = (const float*)d_in[7];
    const float* B_out = (const float*)d_in[8];
    float* out = (float*)d_out;

    float *p_w1h, *p_w1l, *p_w2h, *p_w2l, *p_xh, *p_xl, *p_c, *p_ah, *p_al;
    cudaGetSymbolAddress((void**)&p_w1h, g_w1h);
    cudaGetSymbolAddress((void**)&p_w1l, g_w1l);
    cudaGetSymbolAddress((void**)&p_w2h, g_w2h);
    cudaGetSymbolAddress((void**)&p_w2l, g_w2l);
    cudaGetSymbolAddress((void**)&p_xh,  g_xh);
    cudaGetSymbolAddress((void**)&p_xl,  g_xl);
    cudaGetSymbolAddress((void**)&p_c,   g_c);
    cudaGetSymbolAddress((void**)&p_ah,  g_ah);
    cudaGetSymbolAddress((void**)&p_al,  g_al);

    const int smem1 = 3 * 2 * (16384 + 128 * 128);   // 196608
    const int smem2 = 4 * 2 * (16384 + 64 * 128);    // 196608
    const int smemF = (128 + 64 + 64 + 128) * 64 * 4; // 98304
    cudaFuncSetAttribute(gemm_tc<128>, cudaFuncAttributeMaxDynamicSharedMemorySize, smem1);
    cudaFuncSetAttribute(gemm_tc<64>,  cudaFuncAttributeMaxDynamicSharedMemorySize, smem2);
    cudaFuncSetAttribute(flash_tc, cudaFuncAttributeMaxDynamicSharedMemorySize, smemF);

    {
        dim3 blk(32, 8);
        dim3 g1(N3E / 32, Ee / 32);
        prep_wt<<<g1, blk>>>(w_in, A_in, B_in, p_w1h, p_w1l, N3E);
        dim3 g2(Ee / 32, Ee / 32);
        prep_wt<<<g2, blk>>>(w_out, A_out, B_out, p_w2h, p_w2l, Ee);
        cvt_x<<<Mrows * Ee / 4 / 256, 256>>>((const float4*)x, (float4*)p_xh, (float4*)p_xl);
    }
    {
        dim3 grid(N3E / 128, Mrows / 128);
        gemm_tc<128><<<grid, 256, smem1>>>(p_xh, p_xl, p_w1h, p_w1l, b_in, p_c, N3E);
    }
    {
        dim3 grid(LLen / 128, Bb * Hh);
        flash_tc<<<grid, 256, smemF>>>();
    }
    {
        dim3 grid(Ee / 64, Mrows / 128);
        gemm_tc<64><<<grid, 256, smem2>>>(p_ah, p_al, p_w2h, p_w2l, b_out, out, Ee);
    }
}